// round 2
// baseline (speedup 1.0000x reference)
#include <cuda_runtime.h>
#include <cuda_bf16.h>
#include <cfloat>
#include <cstddef>

// Problem constants
#define BB 8
#define WW 64
#define NN 128
#define DD 1024
#define PP 512
#define VV 256
#define NBW (BB*WW)          // 512 windows
#define OUTD (DD+VV)         // 1280

// Scratch (device globals; no allocation allowed)
__device__ float g_S  [NBW*DD];    // masked sums per window
__device__ float g_LEN[NBW];       // valid lengths
__device__ float g_WE [NBW*PP];
__device__ float g_Q  [NBW*PP];
__device__ float g_R  [NBW*DD];    // W_k @ q per window
__device__ float g_PB [NBW*NN];    // q . pos_j per window
__device__ float g_POS[NN*PP];     // sinusoidal embedding
__device__ float g_Y  [NBW*DD];    // attn-weighted x sum
__device__ float g_O  [NBW*VV];    // attention outputs

// ---------------------------------------------------------------------------
// Sinusoidal position table: POS[j, i<256] = sin(j*invf[i]), [i>=256] = cos
// invf[i] = 10000^(-(2i)/512) = exp(-(i/256)*ln(10000))
// ---------------------------------------------------------------------------
__global__ void pos_kernel() {
    int idx = blockIdx.x * blockDim.x + threadIdx.x;
    if (idx >= NN * PP) return;
    int j = idx >> 9;        // row 0..127
    int i = idx & 511;       // col 0..511
    const float LOG1E4 = 9.210340371976184f;
    float val;
    if (i < 256) {
        float invf = expf(-((float)i / 256.0f) * LOG1E4);
        val = sinf((float)j * invf);
    } else {
        float invf = expf(-((float)(i - 256) / 256.0f) * LOG1E4);
        val = cosf((float)j * invf);
    }
    g_POS[idx] = val;
}

// ---------------------------------------------------------------------------
// Kernel 1: per-window masked sum + length + fused copy x -> out[..., :1024]
// grid = 512 (one block per window), 256 threads, float4 over D
// ---------------------------------------------------------------------------
__global__ void __launch_bounds__(256) k1_sum_copy(
    const float* __restrict__ x, const int* __restrict__ mask,
    float* __restrict__ out)
{
    int bw = blockIdx.x;
    int t  = threadIdx.x;   // 0..255, each owns dims [4t, 4t+4)
    __shared__ int smask[NN];
    if (t < NN) smask[t] = mask[bw * NN + t];
    __syncthreads();

    const float4* x4 = (const float4*)(x + (size_t)bw * NN * DD);
    float4* out4 = (float4*)out;
    float4 acc = make_float4(0.f, 0.f, 0.f, 0.f);
    #pragma unroll 4
    for (int j = 0; j < NN; j++) {
        float4 v = x4[j * (DD/4) + t];
        out4[(size_t)(bw * NN + j) * (OUTD/4) + t] = v;   // copy into concat slot
        if (smask[j] == 0) {
            acc.x += v.x; acc.y += v.y; acc.z += v.z; acc.w += v.w;
        }
    }
    ((float4*)g_S)[bw * (DD/4) + t] = acc;
    if (t == 0) {
        int c = 0;
        #pragma unroll
        for (int j = 0; j < NN; j++) c += (smask[j] == 0);
        g_LEN[bw] = fmaxf((float)c, 1.0f);
    }
}

// ---------------------------------------------------------------------------
// Generic small tiled GEMM: C[M,N] = A[M,K] @ (TB ? B[N,K]^T : B[K,N])
// EPI==1: C = relu(acc / lenv[row])
// 64x64 tile, BK=16, 256 threads, 4x4 per-thread microtile.
// All of M,N divisible by 64 and K by 16 for our sizes.
// ---------------------------------------------------------------------------
template<bool TB, int EPI>
__global__ void __launch_bounds__(256) gemm_k(
    const float* __restrict__ A, const float* __restrict__ B,
    float* __restrict__ C, int M, int N, int K,
    const float* __restrict__ lenv)
{
    __shared__ float As[16][68];
    __shared__ float Bs[16][68];
    int tid = threadIdx.x;
    int row0 = blockIdx.y * 64;
    int col0 = blockIdx.x * 64;
    int ty = tid >> 4, tx = tid & 15;
    float acc[4][4] = {};

    for (int k0 = 0; k0 < K; k0 += 16) {
        #pragma unroll
        for (int i = 0; i < 4; i++) {
            int m = (tid >> 4) + 16 * i;
            int k = tid & 15;
            As[k][m] = A[(size_t)(row0 + m) * K + k0 + k];
        }
        if (!TB) {
            #pragma unroll
            for (int i = 0; i < 4; i++) {
                int k = (tid >> 6) + 4 * i;
                int n = tid & 63;
                Bs[k][n] = B[(size_t)(k0 + k) * N + col0 + n];
            }
        } else {
            #pragma unroll
            for (int i = 0; i < 4; i++) {
                int n = (tid >> 4) + 16 * i;
                int k = tid & 15;
                Bs[k][n] = B[(size_t)(col0 + n) * K + k0 + k];
            }
        }
        __syncthreads();
        #pragma unroll
        for (int kk = 0; kk < 16; kk++) {
            float a[4], b[4];
            #pragma unroll
            for (int i = 0; i < 4; i++) a[i] = As[kk][ty + 16 * i];
            #pragma unroll
            for (int j = 0; j < 4; j++) b[j] = Bs[kk][tx + 16 * j];
            #pragma unroll
            for (int i = 0; i < 4; i++)
                #pragma unroll
                for (int j = 0; j < 4; j++)
                    acc[i][j] += a[i] * b[j];
        }
        __syncthreads();
    }

    #pragma unroll
    for (int i = 0; i < 4; i++) {
        int m = row0 + ty + 16 * i;
        float inv = 1.0f;
        if (EPI == 1) inv = 1.0f / lenv[m];
        #pragma unroll
        for (int j = 0; j < 4; j++) {
            int n = col0 + tx + 16 * j;
            float v = acc[i][j];
            if (EPI == 1) v = fmaxf(v * inv, 0.0f);
            C[(size_t)m * N + n] = v;
        }
    }
}

// ---------------------------------------------------------------------------
// Kernel 3: per-window attention.
// dots_j = (x_j . r + pos_scale * PB[j]) * P^-0.5  (masked -> -FLT_MAX)
// softmax over 128, then y = sum_j attn_j * x_j  -> g_Y
// grid = 512, 256 threads (8 warps).
// ---------------------------------------------------------------------------
__global__ void __launch_bounds__(256) k3_attn(
    const float* __restrict__ x, const int* __restrict__ mask,
    const float* __restrict__ ps_ptr)
{
    int bw = blockIdx.x;
    int t = threadIdx.x;
    int warp = t >> 5, lane = t & 31;
    __shared__ float sr[DD];
    __shared__ float sdots[NN];
    __shared__ float red[NN];
    __shared__ float s_m, s_sum;

    ((float4*)sr)[t] = ((const float4*)(g_R + (size_t)bw * DD))[t];
    __syncthreads();

    const float* xw = x + (size_t)bw * NN * DD;
    float ps = ps_ptr[0];
    const float rs = 0.044194173824159216f;   // 512^-0.5

    // dots: one warp per row, 16 rows per warp
    for (int j = warp; j < NN; j += 8) {
        const float4* row = (const float4*)(xw + (size_t)j * DD);
        const float4* r4  = (const float4*)sr;
        float s = 0.f;
        #pragma unroll
        for (int it = 0; it < 8; it++) {
            float4 v = row[lane + it * 32];
            float4 r = r4 [lane + it * 32];
            s += v.x*r.x + v.y*r.y + v.z*r.z + v.w*r.w;
        }
        #pragma unroll
        for (int o = 16; o > 0; o >>= 1) s += __shfl_xor_sync(0xffffffffu, s, o);
        if (lane == 0) {
            float d;
            if (mask[bw * NN + j] != 0) d = -FLT_MAX;
            else d = (s + ps * g_PB[bw * NN + j]) * rs;
            sdots[j] = d;
        }
    }
    __syncthreads();

    // softmax over 128 values
    if (t < NN) red[t] = sdots[t];
    __syncthreads();
    for (int s = 64; s > 0; s >>= 1) {
        if (t < s) red[t] = fmaxf(red[t], red[t + s]);
        __syncthreads();
    }
    if (t == 0) s_m = red[0];
    __syncthreads();
    float m = s_m;
    if (t < NN) { float e = expf(sdots[t] - m); sdots[t] = e; red[t] = e; }
    __syncthreads();
    for (int s = 64; s > 0; s >>= 1) {
        if (t < s) red[t] += red[t + s];
        __syncthreads();
    }
    if (t == 0) s_sum = red[0];
    __syncthreads();
    float inv = 1.0f / s_sum;

    // weighted sum over rows (x tile is L2-hot from the dots pass)
    float4 acc = make_float4(0.f, 0.f, 0.f, 0.f);
    const float4* x4 = (const float4*)xw;
    #pragma unroll 4
    for (int j = 0; j < NN; j++) {
        float a = sdots[j] * inv;
        float4 v = x4[j * (DD/4) + t];
        acc.x += a*v.x; acc.y += a*v.y; acc.z += a*v.z; acc.w += a*v.w;
    }
    ((float4*)(g_Y + (size_t)bw * DD))[t] = acc;
}

// ---------------------------------------------------------------------------
// Kernel 5: bos-shifted broadcast into out[..., 1024:1280]
// window 0 gets bos, window w gets O[w-1]; broadcast over the 128 rows.
// ---------------------------------------------------------------------------
__global__ void __launch_bounds__(256) k5_bcast(
    const float* __restrict__ bos, float* __restrict__ out)
{
    int bw = blockIdx.x;
    int w  = bw & (WW - 1);
    int t  = threadIdx.x;   // 0..255 = v index
    float val = (w == 0) ? bos[t] : g_O[(size_t)(bw - 1) * VV + t];
    float* base = out + (size_t)bw * NN * OUTD + DD + t;
    #pragma unroll 4
    for (int j = 0; j < NN; j++) base[(size_t)j * OUTD] = val;
}

// ---------------------------------------------------------------------------
extern "C" void kernel_launch(void* const* d_in, const int* in_sizes, int n_in,
                              void* d_out, int out_size) {
    const float* x    = (const float*)d_in[0];
    const int*   mask = (const int*)  d_in[1];
    const float* W_in = (const float*)d_in[2];
    const float* W_q  = (const float*)d_in[3];
    const float* W_k  = (const float*)d_in[4];
    const float* W_v  = (const float*)d_in[5];
    const float* psc  = (const float*)d_in[6];
    const float* bos  = (const float*)d_in[7];
    float* out = (float*)d_out;

    float *pS, *pLEN, *pWE, *pQ, *pR, *pPB, *pPOS, *pY, *pO;
    cudaGetSymbolAddress((void**)&pS,   g_S);
    cudaGetSymbolAddress((void**)&pLEN, g_LEN);
    cudaGetSymbolAddress((void**)&pWE,  g_WE);
    cudaGetSymbolAddress((void**)&pQ,   g_Q);
    cudaGetSymbolAddress((void**)&pR,   g_R);
    cudaGetSymbolAddress((void**)&pPB,  g_PB);
    cudaGetSymbolAddress((void**)&pPOS, g_POS);
    cudaGetSymbolAddress((void**)&pY,   g_Y);
    cudaGetSymbolAddress((void**)&pO,   g_O);

    pos_kernel<<<(NN*PP + 255)/256, 256>>>();
    k1_sum_copy<<<NBW, 256>>>(x, mask, out);

    // WE = relu((S @ W_in) / len)         [512,512] = [512,1024]@[1024,512]
    gemm_k<false,1><<<dim3(PP/64,  NBW/64), 256>>>(pS,  W_in, pWE, NBW, PP, DD, pLEN);
    // Q = WE @ W_q                         [512,512]
    gemm_k<false,0><<<dim3(PP/64,  NBW/64), 256>>>(pWE, W_q,  pQ,  NBW, PP, PP, nullptr);
    // R = Q @ W_k^T                        [512,1024], W_k stored [1024,512]
    gemm_k<true, 0><<<dim3(DD/64,  NBW/64), 256>>>(pQ,  W_k,  pR,  NBW, DD, PP, nullptr);
    // PB = Q @ POS^T                       [512,128], POS stored [128,512]
    gemm_k<true, 0><<<dim3(NN/64,  NBW/64), 256>>>(pQ,  pPOS, pPB, NBW, NN, PP, nullptr);

    k3_attn<<<NBW, 256>>>(x, mask, psc);

    // O = Y @ W_v                          [512,256] = [512,1024]@[1024,256]
    gemm_k<false,0><<<dim3(VV/64,  NBW/64), 256>>>(pY,  W_v,  pO,  NBW, VV, DD, nullptr);

    k5_bcast<<<NBW, 256>>>(bos, out);
}

// round 5
// speedup vs baseline: 1.6777x; 1.6777x over previous
#include <cuda_runtime.h>
#include <cuda_bf16.h>
#include <cfloat>
#include <cstddef>

// Problem constants
#define BB 8
#define WW 64
#define NN 128
#define DD 1024
#define PP 512
#define VV 256
#define NBW (BB*WW)          // 512 windows
#define OUTD (DD+VV)         // 1280
#define NKB (DD+NN)          // 1152 combined W_k rows + pos rows

// Scratch (device globals; no allocation allowed)
__device__ float g_S  [NBW*DD];    // masked sums per window
__device__ float g_LEN[NBW];       // valid lengths
__device__ float g_WE [NBW*PP];
__device__ float g_Q  [NBW*PP];
__device__ float g_KB [NKB*PP];    // [W_k(1024 rows); POS(128 rows)] x 512
__device__ float g_RPB[NBW*NKB];   // per window: [r(1024) | pb(128)]
__device__ float g_Y  [NBW*DD];    // attn-weighted x sum
__device__ float g_O  [NBW*VV];    // attention outputs

// ---------------------------------------------------------------------------
// prep: copy W_k into g_KB rows [0,1024) and fill sinusoidal pos rows [1024,1152)
// POS[j, i<256] = sin(j*invf[i]), [i>=256] = cos(j*invf[i-256])
// ---------------------------------------------------------------------------
__global__ void prep_kernel(const float* __restrict__ Wk) {
    int idx = blockIdx.x * blockDim.x + threadIdx.x;
    if (idx >= NKB * PP) return;
    int row = idx >> 9;      // 0..1151
    int i   = idx & 511;
    if (row < DD) {
        g_KB[idx] = Wk[idx];
    } else {
        int j = row - DD;    // pos row 0..127
        const float LOG1E4 = 9.210340371976184f;
        float val;
        if (i < 256) {
            float invf = expf(-((float)i / 256.0f) * LOG1E4);
            val = sinf((float)j * invf);
        } else {
            float invf = expf(-((float)(i - 256) / 256.0f) * LOG1E4);
            val = cosf((float)j * invf);
        }
        g_KB[idx] = val;
    }
}

// ---------------------------------------------------------------------------
// Kernel 1: per-window masked sum + length + fused copy x -> out[..., :1024]
// ---------------------------------------------------------------------------
__global__ void __launch_bounds__(256) k1_sum_copy(
    const float* __restrict__ x, const int* __restrict__ mask,
    float* __restrict__ out)
{
    int bw = blockIdx.x;
    int t  = threadIdx.x;
    __shared__ int smask[NN];
    if (t < NN) smask[t] = mask[bw * NN + t];
    __syncthreads();

    const float4* x4 = (const float4*)(x + (size_t)bw * NN * DD);
    float4* out4 = (float4*)out;
    float4 acc = make_float4(0.f, 0.f, 0.f, 0.f);
    #pragma unroll 4
    for (int j = 0; j < NN; j++) {
        float4 v = x4[j * (DD/4) + t];
        out4[(size_t)(bw * NN + j) * (OUTD/4) + t] = v;
        if (smask[j] == 0) {
            acc.x += v.x; acc.y += v.y; acc.z += v.z; acc.w += v.w;
        }
    }
    ((float4*)g_S)[bw * (DD/4) + t] = acc;
    if (t == 0) {
        int c = 0;
        #pragma unroll
        for (int j = 0; j < NN; j++) c += (smask[j] == 0);
        g_LEN[bw] = fmaxf((float)c, 1.0f);
    }
}

// ---------------------------------------------------------------------------
// GEMM v2: C[M,N] = A[M,K] @ (TB ? B[N,K]^T : B[K,N]), ldc row stride of C.
// Tile 32x64, 128 threads, 4x4 microtile, BK=16, double-buffered smem,
// register-staged global prefetch, single __syncthreads per stage.
// Requires: M%32==0, N%64==0, K%16==0.
// EPI==1: C = relu(acc / lenv[row])
// ---------------------------------------------------------------------------
template<bool TB, int EPI>
__global__ void __launch_bounds__(128) gemm2(
    const float* __restrict__ A, const float* __restrict__ B,
    float* __restrict__ C, int M, int N, int K, int ldc,
    const float* __restrict__ lenv)
{
    __shared__ float As[2][16][33];
    __shared__ float Bs[2][16][68];
    const int tid  = threadIdx.x;
    const int row0 = blockIdx.y * 32;
    const int col0 = blockIdx.x * 64;
    const int ty = tid >> 4;          // 0..7
    const int tx = tid & 15;          // 0..15

    // A staging: thread loads float4 at row (tid>>2), k offset (tid&3)*4
    const int arow = tid >> 2;        // 0..31
    const int akc  = (tid & 3) << 2;  // 0,4,8,12
    const float* Ag = A + (size_t)(row0 + arow) * K + akc;

    // B staging
    const int bk  = tid >> 3;         // !TB: 0..15
    const int bn  = (tid & 7) << 3;   // !TB: 0,8,..,56
    const int tn  = tid & 63;         // TB: 0..63
    const int tkh = (tid >> 6) << 3;  // TB: 0 or 8

    float acc[4][4] = {};
    float4 ra, rb0, rb1;

    // ---- prologue: stage 0 ----
    ra = *(const float4*)Ag;
    if (!TB) {
        const float* bp = B + (size_t)bk * N + col0 + bn;
        rb0 = *(const float4*)bp;
        rb1 = *(const float4*)(bp + 4);
    } else {
        const float* bp = B + (size_t)(col0 + tn) * K + tkh;
        rb0 = *(const float4*)bp;
        rb1 = *(const float4*)(bp + 4);
    }
    As[0][akc+0][arow] = ra.x; As[0][akc+1][arow] = ra.y;
    As[0][akc+2][arow] = ra.z; As[0][akc+3][arow] = ra.w;
    if (!TB) {
        *(float4*)&Bs[0][bk][bn]     = rb0;
        *(float4*)&Bs[0][bk][bn + 4] = rb1;
    } else {
        Bs[0][tkh+0][tn] = rb0.x; Bs[0][tkh+1][tn] = rb0.y;
        Bs[0][tkh+2][tn] = rb0.z; Bs[0][tkh+3][tn] = rb0.w;
        Bs[0][tkh+4][tn] = rb1.x; Bs[0][tkh+5][tn] = rb1.y;
        Bs[0][tkh+6][tn] = rb1.z; Bs[0][tkh+7][tn] = rb1.w;
    }
    __syncthreads();

    const int nst = K >> 4;
    for (int s = 0; s < nst; s++) {
        const int cur = s & 1;
        // prefetch next stage into registers
        if (s + 1 < nst) {
            const int k0 = (s + 1) << 4;
            ra = *(const float4*)(Ag + k0);
            if (!TB) {
                const float* bp = B + (size_t)(k0 + bk) * N + col0 + bn;
                rb0 = *(const float4*)bp;
                rb1 = *(const float4*)(bp + 4);
            } else {
                const float* bp = B + (size_t)(col0 + tn) * K + k0 + tkh;
                rb0 = *(const float4*)bp;
                rb1 = *(const float4*)(bp + 4);
            }
        }
        // compute current stage
        #pragma unroll
        for (int kk = 0; kk < 16; kk++) {
            float a[4], b[4];
            #pragma unroll
            for (int i = 0; i < 4; i++) a[i] = As[cur][kk][ty + 8 * i];
            #pragma unroll
            for (int j = 0; j < 4; j++) b[j] = Bs[cur][kk][tx + 16 * j];
            #pragma unroll
            for (int i = 0; i < 4; i++)
                #pragma unroll
                for (int j = 0; j < 4; j++)
                    acc[i][j] = fmaf(a[i], b[j], acc[i][j]);
        }
        // store next stage (other buffer) then one sync
        if (s + 1 < nst) {
            const int nxt = cur ^ 1;
            As[nxt][akc+0][arow] = ra.x; As[nxt][akc+1][arow] = ra.y;
            As[nxt][akc+2][arow] = ra.z; As[nxt][akc+3][arow] = ra.w;
            if (!TB) {
                *(float4*)&Bs[nxt][bk][bn]     = rb0;
                *(float4*)&Bs[nxt][bk][bn + 4] = rb1;
            } else {
                Bs[nxt][tkh+0][tn] = rb0.x; Bs[nxt][tkh+1][tn] = rb0.y;
                Bs[nxt][tkh+2][tn] = rb0.z; Bs[nxt][tkh+3][tn] = rb0.w;
                Bs[nxt][tkh+4][tn] = rb1.x; Bs[nxt][tkh+5][tn] = rb1.y;
                Bs[nxt][tkh+6][tn] = rb1.z; Bs[nxt][tkh+7][tn] = rb1.w;
            }
            __syncthreads();
        }
    }

    // epilogue
    #pragma unroll
    for (int i = 0; i < 4; i++) {
        const int m = row0 + ty + 8 * i;
        float inv = 1.0f;
        if (EPI == 1) inv = 1.0f / lenv[m];
        #pragma unroll
        for (int j = 0; j < 4; j++) {
            const int n = col0 + tx + 16 * j;
            float v = acc[i][j];
            if (EPI == 1) v = fmaxf(v * inv, 0.0f);
            C[(size_t)m * ldc + n] = v;
        }
    }
}

// ---------------------------------------------------------------------------
// Kernel 3: per-window attention using fused RPB = [r | pb].
// ---------------------------------------------------------------------------
__global__ void __launch_bounds__(256) k3_attn(
    const float* __restrict__ x, const int* __restrict__ mask,
    const float* __restrict__ ps_ptr)
{
    int bw = blockIdx.x;
    int t = threadIdx.x;
    int warp = t >> 5, lane = t & 31;
    __shared__ float sr[DD];
    __shared__ float sdots[NN];
    __shared__ float red[NN];
    __shared__ float s_m, s_sum;

    const float* rpb = g_RPB + (size_t)bw * NKB;
    ((float4*)sr)[t] = ((const float4*)rpb)[t];
    __syncthreads();

    const float* xw = x + (size_t)bw * NN * DD;
    float ps = ps_ptr[0];
    const float rs = 0.044194173824159216f;   // 512^-0.5

    for (int j = warp; j < NN; j += 8) {
        const float4* row = (const float4*)(xw + (size_t)j * DD);
        const float4* r4  = (const float4*)sr;
        float s = 0.f;
        #pragma unroll
        for (int it = 0; it < 8; it++) {
            float4 v = row[lane + it * 32];
            float4 r = r4 [lane + it * 32];
            s += v.x*r.x + v.y*r.y + v.z*r.z + v.w*r.w;
        }
        #pragma unroll
        for (int o = 16; o > 0; o >>= 1) s += __shfl_xor_sync(0xffffffffu, s, o);
        if (lane == 0) {
            float d;
            if (mask[bw * NN + j] != 0) d = -FLT_MAX;
            else d = (s + ps * rpb[DD + j]) * rs;
            sdots[j] = d;
        }
    }
    __syncthreads();

    if (t < NN) red[t] = sdots[t];
    __syncthreads();
    for (int s = 64; s > 0; s >>= 1) {
        if (t < s) red[t] = fmaxf(red[t], red[t + s]);
        __syncthreads();
    }
    if (t == 0) s_m = red[0];
    __syncthreads();
    float m = s_m;
    if (t < NN) { float e = expf(sdots[t] - m); sdots[t] = e; red[t] = e; }
    __syncthreads();
    for (int s = 64; s > 0; s >>= 1) {
        if (t < s) red[t] += red[t + s];
        __syncthreads();
    }
    if (t == 0) s_sum = red[0];
    __syncthreads();
    float inv = 1.0f / s_sum;

    float4 acc = make_float4(0.f, 0.f, 0.f, 0.f);
    const float4* x4 = (const float4*)xw;
    #pragma unroll 4
    for (int j = 0; j < NN; j++) {
        float a = sdots[j] * inv;
        float4 v = x4[j * (DD/4) + t];
        acc.x += a*v.x; acc.y += a*v.y; acc.z += a*v.z; acc.w += a*v.w;
    }
    ((float4*)(g_Y + (size_t)bw * DD))[t] = acc;
}

// ---------------------------------------------------------------------------
// Kernel 5: bos-shifted broadcast into out[..., 1024:1280]
// ---------------------------------------------------------------------------
__global__ void __launch_bounds__(256) k5_bcast(
    const float* __restrict__ bos, float* __restrict__ out)
{
    int bw = blockIdx.x;
    int w  = bw & (WW - 1);
    int t  = threadIdx.x;
    float val = (w == 0) ? bos[t] : g_O[(size_t)(bw - 1) * VV + t];
    float* base = out + (size_t)bw * NN * OUTD + DD + t;
    #pragma unroll 4
    for (int j = 0; j < NN; j++) base[(size_t)j * OUTD] = val;
}

// ---------------------------------------------------------------------------
extern "C" void kernel_launch(void* const* d_in, const int* in_sizes, int n_in,
                              void* d_out, int out_size) {
    const float* x    = (const float*)d_in[0];
    const int*   mask = (const int*)  d_in[1];
    const float* W_in = (const float*)d_in[2];
    const float* W_q  = (const float*)d_in[3];
    const float* W_k  = (const float*)d_in[4];
    const float* W_v  = (const float*)d_in[5];
    const float* psc  = (const float*)d_in[6];
    const float* bos  = (const float*)d_in[7];
    float* out = (float*)d_out;

    float *pS, *pLEN, *pWE, *pQ, *pKB, *pRPB, *pY, *pO;
    cudaGetSymbolAddress((void**)&pS,   g_S);
    cudaGetSymbolAddress((void**)&pLEN, g_LEN);
    cudaGetSymbolAddress((void**)&pWE,  g_WE);
    cudaGetSymbolAddress((void**)&pQ,   g_Q);
    cudaGetSymbolAddress((void**)&pKB,  g_KB);
    cudaGetSymbolAddress((void**)&pRPB, g_RPB);
    cudaGetSymbolAddress((void**)&pY,   g_Y);
    cudaGetSymbolAddress((void**)&pO,   g_O);

    prep_kernel<<<(NKB*PP + 255)/256, 256>>>(W_k);
    k1_sum_copy<<<NBW, 256>>>(x, mask, out);

    // WE = relu((S @ W_in) / len)   [512,512], K=1024   grid (8,16)=128
    gemm2<false,1><<<dim3(PP/64,  NBW/32), 128>>>(pS,  W_in, pWE,  NBW, PP,  DD, PP,  pLEN);
    // Q = WE @ W_q                  [512,512], K=512    grid 128
    gemm2<false,0><<<dim3(PP/64,  NBW/32), 128>>>(pWE, W_q,  pQ,   NBW, PP,  PP, PP,  nullptr);
    // RPB = Q @ KB^T                [512,1152], K=512   grid (18,16)=288
    gemm2<true, 0><<<dim3(NKB/64, NBW/32), 128>>>(pQ,  pKB,  pRPB, NBW, NKB, PP, NKB, nullptr);

    k3_attn<<<NBW, 256>>>(x, mask, psc);

    // O = Y @ W_v                   [512,256], K=1024   grid (4,16)=64
    gemm2<false,0><<<dim3(VV/64,  NBW/32), 128>>>(pY,  W_v,  pO,   NBW, VV,  DD, VV,  nullptr);

    k5_bcast<<<NBW, 256>>>(bos, out);
}

// round 6
// speedup vs baseline: 2.0602x; 1.2280x over previous
#include <cuda_runtime.h>
#include <cuda_bf16.h>
#include <cfloat>
#include <cstddef>

// Problem constants
#define BB 8
#define WW 64
#define NN 128
#define DD 1024
#define PP 512
#define VV 256
#define NBW (BB*WW)          // 512 windows
#define OUTD (DD+VV)         // 1280
#define NKB (DD+NN)          // 1152 combined W_k rows + pos rows

// Scratch (device globals; no allocation allowed)
__device__ float g_S   [NBW*DD];     // masked sums per window
__device__ float g_LEN [NBW];        // valid lengths
__device__ float g_WE  [NBW*PP];
__device__ float g_Q   [NBW*PP];
__device__ float g_KB  [NKB*PP];     // [W_k(1024 rows); POS(128 rows)] x 512
__device__ float g_RPB [NBW*NKB];    // per window: [r(1024) | pb(128)]
__device__ float g_Y   [NBW*DD];     // attn-weighted x sum
__device__ float g_O   [NBW*VV];     // attention outputs
__device__ float g_PART[2*NBW*NKB];  // split-K partials (max 512*1152*2)

// ---------------------------------------------------------------------------
// prep: copy W_k into g_KB rows [0,1024) and fill sinusoidal pos rows
// ---------------------------------------------------------------------------
__global__ void prep_kernel(const float* __restrict__ Wk) {
    int idx = blockIdx.x * blockDim.x + threadIdx.x;
    if (idx >= NKB * PP) return;
    int row = idx >> 9;      // 0..1151
    int i   = idx & 511;
    if (row < DD) {
        g_KB[idx] = Wk[idx];
    } else {
        int j = row - DD;    // pos row 0..127
        const float LOG1E4 = 9.210340371976184f;
        float val;
        if (i < 256) {
            float invf = expf(-((float)i / 256.0f) * LOG1E4);
            val = sinf((float)j * invf);
        } else {
            float invf = expf(-((float)(i - 256) / 256.0f) * LOG1E4);
            val = cosf((float)j * invf);
        }
        g_KB[idx] = val;
    }
}

// ---------------------------------------------------------------------------
// Kernel 1: per-window masked sum + length + fused copy x -> out[..., :1024]
// ---------------------------------------------------------------------------
__global__ void __launch_bounds__(256) k1_sum_copy(
    const float* __restrict__ x, const int* __restrict__ mask,
    float* __restrict__ out)
{
    int bw = blockIdx.x;
    int t  = threadIdx.x;
    __shared__ int smask[NN];
    if (t < NN) smask[t] = mask[bw * NN + t];
    __syncthreads();

    const float4* x4 = (const float4*)(x + (size_t)bw * NN * DD);
    float4* out4 = (float4*)out;
    float4 acc = make_float4(0.f, 0.f, 0.f, 0.f);
    #pragma unroll 4
    for (int j = 0; j < NN; j++) {
        float4 v = x4[j * (DD/4) + t];
        out4[(size_t)(bw * NN + j) * (OUTD/4) + t] = v;
        if (smask[j] == 0) {
            acc.x += v.x; acc.y += v.y; acc.z += v.z; acc.w += v.w;
        }
    }
    ((float4*)g_S)[bw * (DD/4) + t] = acc;
    if (t == 0) {
        int c = 0;
        #pragma unroll
        for (int j = 0; j < NN; j++) c += (smask[j] == 0);
        g_LEN[bw] = fmaxf((float)c, 1.0f);
    }
}

// ---------------------------------------------------------------------------
// Split-K GEMM: part[z] += A[M, kchunk slice] @ B-slice.
//   C_full[M,N] = sum_z part[z][M,N]   (reduced by reduce_k)
// TB=0: B is [K,N] (ldb = N); TB=1: B is [N,K] (ldb = K).
// Tile 32x64, 128 threads, 4x4 microtile, BK=16, double-buffered smem,
// register-staged global prefetch, single __syncthreads per stage.
// ---------------------------------------------------------------------------
template<bool TB>
__global__ void __launch_bounds__(128) gemm_sk(
    const float* __restrict__ A, const float* __restrict__ B,
    float* __restrict__ part, int M, int N, int lda, int ldb, int Kchunk)
{
    __shared__ float As[2][16][33];
    __shared__ float Bs[2][16][68];
    const int tid   = threadIdx.x;
    const int row0  = blockIdx.y * 32;
    const int col0  = blockIdx.x * 64;
    const int kbase = blockIdx.z * Kchunk;
    const int ty = tid >> 4;          // 0..7
    const int tx = tid & 15;          // 0..15

    const int arow = tid >> 2;        // 0..31
    const int akc  = (tid & 3) << 2;  // 0,4,8,12
    const float* Ag = A + (size_t)(row0 + arow) * lda + kbase + akc;

    const int bk  = tid >> 3;         // !TB: 0..15
    const int bn  = (tid & 7) << 3;   // !TB: 0,8,..,56
    const int tn  = tid & 63;         // TB: 0..63
    const int tkh = (tid >> 6) << 3;  // TB: 0 or 8

    float acc[4][4] = {};
    float4 ra, rb0, rb1;

    // ---- prologue: stage 0 ----
    ra = *(const float4*)Ag;
    if (!TB) {
        const float* bp = B + (size_t)(kbase + bk) * ldb + col0 + bn;
        rb0 = *(const float4*)bp;
        rb1 = *(const float4*)(bp + 4);
    } else {
        const float* bp = B + (size_t)(col0 + tn) * ldb + kbase + tkh;
        rb0 = *(const float4*)bp;
        rb1 = *(const float4*)(bp + 4);
    }
    As[0][akc+0][arow] = ra.x; As[0][akc+1][arow] = ra.y;
    As[0][akc+2][arow] = ra.z; As[0][akc+3][arow] = ra.w;
    if (!TB) {
        *(float4*)&Bs[0][bk][bn]     = rb0;
        *(float4*)&Bs[0][bk][bn + 4] = rb1;
    } else {
        Bs[0][tkh+0][tn] = rb0.x; Bs[0][tkh+1][tn] = rb0.y;
        Bs[0][tkh+2][tn] = rb0.z; Bs[0][tkh+3][tn] = rb0.w;
        Bs[0][tkh+4][tn] = rb1.x; Bs[0][tkh+5][tn] = rb1.y;
        Bs[0][tkh+6][tn] = rb1.z; Bs[0][tkh+7][tn] = rb1.w;
    }
    __syncthreads();

    const int nst = Kchunk >> 4;
    for (int s = 0; s < nst; s++) {
        const int cur = s & 1;
        if (s + 1 < nst) {
            const int k0 = kbase + ((s + 1) << 4);
            ra = *(const float4*)(Ag + ((s + 1) << 4));
            if (!TB) {
                const float* bp = B + (size_t)(k0 + bk) * ldb + col0 + bn;
                rb0 = *(const float4*)bp;
                rb1 = *(const float4*)(bp + 4);
            } else {
                const float* bp = B + (size_t)(col0 + tn) * ldb + k0 + tkh;
                rb0 = *(const float4*)bp;
                rb1 = *(const float4*)(bp + 4);
            }
        }
        #pragma unroll
        for (int kk = 0; kk < 16; kk++) {
            float a[4], b[4];
            #pragma unroll
            for (int i = 0; i < 4; i++) a[i] = As[cur][kk][ty + 8 * i];
            #pragma unroll
            for (int j = 0; j < 4; j++) b[j] = Bs[cur][kk][tx + 16 * j];
            #pragma unroll
            for (int i = 0; i < 4; i++)
                #pragma unroll
                for (int j = 0; j < 4; j++)
                    acc[i][j] = fmaf(a[i], b[j], acc[i][j]);
        }
        if (s + 1 < nst) {
            const int nxt = cur ^ 1;
            As[nxt][akc+0][arow] = ra.x; As[nxt][akc+1][arow] = ra.y;
            As[nxt][akc+2][arow] = ra.z; As[nxt][akc+3][arow] = ra.w;
            if (!TB) {
                *(float4*)&Bs[nxt][bk][bn]     = rb0;
                *(float4*)&Bs[nxt][bk][bn + 4] = rb1;
            } else {
                Bs[nxt][tkh+0][tn] = rb0.x; Bs[nxt][tkh+1][tn] = rb0.y;
                Bs[nxt][tkh+2][tn] = rb0.z; Bs[nxt][tkh+3][tn] = rb0.w;
                Bs[nxt][tkh+4][tn] = rb1.x; Bs[nxt][tkh+5][tn] = rb1.y;
                Bs[nxt][tkh+6][tn] = rb1.z; Bs[nxt][tkh+7][tn] = rb1.w;
            }
            __syncthreads();
        }
    }

    float* Cp = part + (size_t)blockIdx.z * M * N;
    #pragma unroll
    for (int i = 0; i < 4; i++) {
        const int m = row0 + ty + 8 * i;
        #pragma unroll
        for (int j = 0; j < 4; j++) {
            const int n = col0 + tx + 16 * j;
            Cp[(size_t)m * N + n] = acc[i][j];
        }
    }
}

// ---------------------------------------------------------------------------
// reduce_k: C = sum of SPLIT partials; EPI==1: relu(sum / lenv[row])
// float4-vectorized over M*N elements (layout shared: row stride N).
// ---------------------------------------------------------------------------
template<int EPI>
__global__ void __launch_bounds__(256) reduce_k(
    const float* __restrict__ part, float* __restrict__ C,
    int MN, int N, int SPLIT, const float* __restrict__ lenv)
{
    int idx4 = blockIdx.x * blockDim.x + threadIdx.x;
    if (idx4 * 4 >= MN) return;
    const float4* p4 = (const float4*)part;
    float4 s = p4[idx4];
    for (int z = 1; z < SPLIT; z++) {
        float4 v = p4[(size_t)z * (MN / 4) + idx4];
        s.x += v.x; s.y += v.y; s.z += v.z; s.w += v.w;
    }
    if (EPI == 1) {
        int row = (idx4 * 4) / N;
        float inv = 1.0f / lenv[row];
        s.x = fmaxf(s.x * inv, 0.f); s.y = fmaxf(s.y * inv, 0.f);
        s.z = fmaxf(s.z * inv, 0.f); s.w = fmaxf(s.w * inv, 0.f);
    }
    ((float4*)C)[idx4] = s;
}

// ---------------------------------------------------------------------------
// Kernel 3: per-window attention using fused RPB = [r | pb].
// ---------------------------------------------------------------------------
__global__ void __launch_bounds__(256) k3_attn(
    const float* __restrict__ x, const int* __restrict__ mask,
    const float* __restrict__ ps_ptr)
{
    int bw = blockIdx.x;
    int t = threadIdx.x;
    int warp = t >> 5, lane = t & 31;
    __shared__ float sr[DD];
    __shared__ float sdots[NN];
    __shared__ float red[NN];
    __shared__ float s_m, s_sum;

    const float* rpb = g_RPB + (size_t)bw * NKB;
    ((float4*)sr)[t] = ((const float4*)rpb)[t];
    __syncthreads();

    const float* xw = x + (size_t)bw * NN * DD;
    float ps = ps_ptr[0];
    const float rs = 0.044194173824159216f;   // 512^-0.5

    for (int j = warp; j < NN; j += 8) {
        const float4* row = (const float4*)(xw + (size_t)j * DD);
        const float4* r4  = (const float4*)sr;
        float s = 0.f;
        #pragma unroll
        for (int it = 0; it < 8; it++) {
            float4 v = row[lane + it * 32];
            float4 r = r4 [lane + it * 32];
            s += v.x*r.x + v.y*r.y + v.z*r.z + v.w*r.w;
        }
        #pragma unroll
        for (int o = 16; o > 0; o >>= 1) s += __shfl_xor_sync(0xffffffffu, s, o);
        if (lane == 0) {
            float d;
            if (mask[bw * NN + j] != 0) d = -FLT_MAX;
            else d = (s + ps * rpb[DD + j]) * rs;
            sdots[j] = d;
        }
    }
    __syncthreads();

    if (t < NN) red[t] = sdots[t];
    __syncthreads();
    for (int s = 64; s > 0; s >>= 1) {
        if (t < s) red[t] = fmaxf(red[t], red[t + s]);
        __syncthreads();
    }
    if (t == 0) s_m = red[0];
    __syncthreads();
    float m = s_m;
    if (t < NN) { float e = expf(sdots[t] - m); sdots[t] = e; red[t] = e; }
    __syncthreads();
    for (int s = 64; s > 0; s >>= 1) {
        if (t < s) red[t] += red[t + s];
        __syncthreads();
    }
    if (t == 0) s_sum = red[0];
    __syncthreads();
    float inv = 1.0f / s_sum;

    float4 acc = make_float4(0.f, 0.f, 0.f, 0.f);
    const float4* x4 = (const float4*)xw;
    #pragma unroll 4
    for (int j = 0; j < NN; j++) {
        float a = sdots[j] * inv;
        float4 v = x4[j * (DD/4) + t];
        acc.x += a*v.x; acc.y += a*v.y; acc.z += a*v.z; acc.w += a*v.w;
    }
    ((float4*)(g_Y + (size_t)bw * DD))[t] = acc;
}

// ---------------------------------------------------------------------------
// Kernel 5: bos-shifted broadcast into out[..., 1024:1280]
// ---------------------------------------------------------------------------
__global__ void __launch_bounds__(256) k5_bcast(
    const float* __restrict__ bos, float* __restrict__ out)
{
    int bw = blockIdx.x;
    int w  = bw & (WW - 1);
    int t  = threadIdx.x;
    float val = (w == 0) ? bos[t] : g_O[(size_t)(bw - 1) * VV + t];
    float* base = out + (size_t)bw * NN * OUTD + DD + t;
    #pragma unroll 4
    for (int j = 0; j < NN; j++) base[(size_t)j * OUTD] = val;
}

// ---------------------------------------------------------------------------
extern "C" void kernel_launch(void* const* d_in, const int* in_sizes, int n_in,
                              void* d_out, int out_size) {
    const float* x    = (const float*)d_in[0];
    const int*   mask = (const int*)  d_in[1];
    const float* W_in = (const float*)d_in[2];
    const float* W_q  = (const float*)d_in[3];
    const float* W_k  = (const float*)d_in[4];
    const float* W_v  = (const float*)d_in[5];
    const float* psc  = (const float*)d_in[6];
    const float* bos  = (const float*)d_in[7];
    float* out = (float*)d_out;

    float *pS, *pLEN, *pWE, *pQ, *pKB, *pRPB, *pY, *pO, *pPART;
    cudaGetSymbolAddress((void**)&pS,    g_S);
    cudaGetSymbolAddress((void**)&pLEN,  g_LEN);
    cudaGetSymbolAddress((void**)&pWE,   g_WE);
    cudaGetSymbolAddress((void**)&pQ,    g_Q);
    cudaGetSymbolAddress((void**)&pKB,   g_KB);
    cudaGetSymbolAddress((void**)&pRPB,  g_RPB);
    cudaGetSymbolAddress((void**)&pY,    g_Y);
    cudaGetSymbolAddress((void**)&pO,    g_O);
    cudaGetSymbolAddress((void**)&pPART, g_PART);

    prep_kernel<<<(NKB*PP + 255)/256, 256>>>(W_k);
    k1_sum_copy<<<NBW, 256>>>(x, mask, out);

    // WE = relu((S @ W_in) / len)   [512,512], K=1024, split 4 -> 512 blocks
    gemm_sk<false><<<dim3(PP/64, NBW/32, 4), 128>>>(pS, W_in, pPART, NBW, PP, DD, PP, 256);
    reduce_k<1><<<(NBW*PP/4 + 255)/256, 256>>>(pPART, pWE, NBW*PP, PP, 4, pLEN);

    // Q = WE @ W_q                  [512,512], K=512, split 4 -> 512 blocks
    gemm_sk<false><<<dim3(PP/64, NBW/32, 4), 128>>>(pWE, W_q, pPART, NBW, PP, PP, PP, 128);
    reduce_k<0><<<(NBW*PP/4 + 255)/256, 256>>>(pPART, pQ, NBW*PP, PP, 4, nullptr);

    // RPB = Q @ KB^T                [512,1152], K=512, split 2 -> 576 blocks
    gemm_sk<true><<<dim3(NKB/64, NBW/32, 2), 128>>>(pQ, pKB, pPART, NBW, NKB, PP, PP, 256);
    reduce_k<0><<<(NBW*NKB/4 + 255)/256, 256>>>(pPART, pRPB, NBW*NKB, NKB, 2, nullptr);

    k3_attn<<<NBW, 256>>>(x, mask, psc);

    // O = Y @ W_v                   [512,256], K=1024, split 8 -> 512 blocks
    gemm_sk<false><<<dim3(VV/64, NBW/32, 8), 128>>>(pY, W_v, pPART, NBW, VV, DD, VV, 128);
    reduce_k<0><<<(NBW*VV/4 + 255)/256, 256>>>(pPART, pO, NBW*VV, VV, 8, nullptr);

    k5_bcast<<<NBW, 256>>>(bos, out);
}

// round 7
// speedup vs baseline: 2.0909x; 1.0149x over previous
#include <cuda_runtime.h>
#include <cuda_bf16.h>
#include <cfloat>
#include <cstddef>

// Problem constants
#define BB 8
#define WW 64
#define NN 128
#define DD 1024
#define PP 512
#define VV 256
#define NBW (BB*WW)          // 512 windows
#define OUTD (DD+VV)         // 1280
#define NKB (DD+NN)          // 1152 combined W_k rows + pos rows
#define CPB 512              // copy blocks embedded per fused launch
#define CROWS 16384          // rows copied per fused launch (4 * 16384 = 65536)

// Scratch (device globals; no allocation allowed)
__device__ float g_S  [NBW*DD];      // masked sums per window
__device__ float g_LEN[NBW];         // valid lengths
__device__ float g_KB [NKB*PP];      // [W_k(1024 rows); POS(128 rows)] x 512
__device__ float g_Y  [NBW*DD];      // attn-weighted x sum
__device__ float g_P1 [2*NBW*NKB];   // partials: WE(4x512x512) / RPB(2x512x1152)
__device__ float g_P2 [4*NBW*PP];    // partials: Q(4x512x512)  / O(8x512x256)

// ---------------------------------------------------------------------------
// prep: W_k rows [0,1024) + sinusoidal pos rows [1024,1152) into g_KB
// ---------------------------------------------------------------------------
__global__ void prep_kernel(const float* __restrict__ Wk) {
    int idx = blockIdx.x * blockDim.x + threadIdx.x;
    if (idx >= NKB * PP) return;
    int row = idx >> 9;      // 0..1151
    int i   = idx & 511;
    if (row < DD) {
        g_KB[idx] = Wk[idx];
    } else {
        int j = row - DD;    // pos row 0..127
        const float LOG1E4 = 9.210340371976184f;
        float val;
        if (i < 256) {
            float invf = expf(-((float)i / 256.0f) * LOG1E4);
            val = sinf((float)j * invf);
        } else {
            float invf = expf(-((float)(i - 256) / 256.0f) * LOG1E4);
            val = cosf((float)j * invf);
        }
        g_KB[idx] = val;
    }
}

// ---------------------------------------------------------------------------
// Kernel 1: per-window masked sum + length (copy moved to fused launches)
// ---------------------------------------------------------------------------
__global__ void __launch_bounds__(256) k1_sum(
    const float* __restrict__ x, const int* __restrict__ mask)
{
    int bw = blockIdx.x;
    int t  = threadIdx.x;
    __shared__ int smask[NN];
    if (t < NN) smask[t] = mask[bw * NN + t];
    __syncthreads();

    const float4* x4 = (const float4*)(x + (size_t)bw * NN * DD);
    float4 acc = make_float4(0.f, 0.f, 0.f, 0.f);
    #pragma unroll 8
    for (int j = 0; j < NN; j++) {
        float4 v = x4[j * (DD/4) + t];
        if (smask[j] == 0) {
            acc.x += v.x; acc.y += v.y; acc.z += v.z; acc.w += v.w;
        }
    }
    ((float4*)g_S)[bw * (DD/4) + t] = acc;
    if (t == 0) {
        int c = 0;
        #pragma unroll
        for (int j = 0; j < NN; j++) c += (smask[j] == 0);
        g_LEN[bw] = fmaxf((float)c, 1.0f);
    }
}

// ---------------------------------------------------------------------------
// Fused GEMM + copy-chunk kernel.
// Blocks [0, CPB): copy 32 rows each of x -> out[..., :1024] (streaming stores).
// Blocks [CPB, ...): split-K GEMM, 32x64 tile, 128 thr, 4x4 microtile, BK=16,
//   double-buffered smem, register prefetch.
// A is read as the sum of ASUM partial slabs (slab stride NBW*lda).
// AEPI==1: A element := relu(sum / lenv[row])  (consumes WE partials).
// Output: partial slab part[bz][M][N] (consumer sums).
// ---------------------------------------------------------------------------
template<bool TB, int ASUM, int AEPI>
__global__ void __launch_bounds__(128) fgemm(
    const float* __restrict__ A, const float* __restrict__ B,
    float* __restrict__ part, int N, int lda, int ldb, int Kchunk,
    int gx, const float* __restrict__ lenv,
    const float* __restrict__ xsrc, float* __restrict__ outdst, int rowBase)
{
    __shared__ float As[2][16][33];
    __shared__ float Bs[2][16][68];
    const int tid = threadIdx.x;

    if (blockIdx.x < CPB) {
        // ---------------- copy path ----------------
        const float4* x4 = (const float4*)xsrc;
        float4* o4 = (float4*)outdst;
        size_t row0 = (size_t)rowBase + (size_t)blockIdx.x * 32;
        #pragma unroll 4
        for (int r = 0; r < 32; r++) {
            size_t row = row0 + r;
            float4 v0 = x4[row * 256 + tid];
            float4 v1 = x4[row * 256 + 128 + tid];
            __stcs(&o4[row * 320 + tid], v0);
            __stcs(&o4[row * 320 + 128 + tid], v1);
        }
        return;
    }

    // ---------------- gemm path ----------------
    const int g   = blockIdx.x - CPB;
    const int bx  = g % gx;
    const int rem = g / gx;
    const int by  = rem & 15;        // M/32 = 16 always (M = 512)
    const int bz  = rem >> 4;
    const int row0  = by * 32;
    const int col0  = bx * 64;
    const int kbase = bz * Kchunk;

    const int ty = tid >> 4;          // 0..7
    const int tx = tid & 15;          // 0..15

    const int arow = tid >> 2;        // 0..31
    const int akc  = (tid & 3) << 2;  // 0,4,8,12
    const size_t AS = (size_t)NBW * lda;
    const float* Ag = A + (size_t)(row0 + arow) * lda + kbase + akc;
    float invlen = 1.0f;
    if (AEPI) invlen = 1.0f / lenv[row0 + arow];

    const int bk  = tid >> 3;         // !TB: 0..15
    const int bn  = (tid & 7) << 3;   // !TB
    const int tn  = tid & 63;         // TB
    const int tkh = (tid >> 6) << 3;  // TB: 0 or 8

    float acc[4][4] = {};
    float4 va[ASUM];
    float4 rb0, rb1;

    // ---- prologue loads (stage 0) ----
    #pragma unroll
    for (int z = 0; z < ASUM; z++) va[z] = *(const float4*)(Ag + (size_t)z * AS);
    if (!TB) {
        const float* bp = B + (size_t)(kbase + bk) * ldb + col0 + bn;
        rb0 = *(const float4*)bp; rb1 = *(const float4*)(bp + 4);
    } else {
        const float* bp = B + (size_t)(col0 + tn) * ldb + kbase + tkh;
        rb0 = *(const float4*)bp; rb1 = *(const float4*)(bp + 4);
    }
    {
        float4 s = va[0];
        #pragma unroll
        for (int z = 1; z < ASUM; z++) { s.x += va[z].x; s.y += va[z].y; s.z += va[z].z; s.w += va[z].w; }
        if (AEPI) {
            s.x = fmaxf(s.x * invlen, 0.f); s.y = fmaxf(s.y * invlen, 0.f);
            s.z = fmaxf(s.z * invlen, 0.f); s.w = fmaxf(s.w * invlen, 0.f);
        }
        As[0][akc+0][arow] = s.x; As[0][akc+1][arow] = s.y;
        As[0][akc+2][arow] = s.z; As[0][akc+3][arow] = s.w;
    }
    if (!TB) {
        *(float4*)&Bs[0][bk][bn]     = rb0;
        *(float4*)&Bs[0][bk][bn + 4] = rb1;
    } else {
        Bs[0][tkh+0][tn] = rb0.x; Bs[0][tkh+1][tn] = rb0.y;
        Bs[0][tkh+2][tn] = rb0.z; Bs[0][tkh+3][tn] = rb0.w;
        Bs[0][tkh+4][tn] = rb1.x; Bs[0][tkh+5][tn] = rb1.y;
        Bs[0][tkh+6][tn] = rb1.z; Bs[0][tkh+7][tn] = rb1.w;
    }
    __syncthreads();

    const int nst = Kchunk >> 4;
    for (int s = 0; s < nst; s++) {
        const int cur = s & 1;
        if (s + 1 < nst) {
            const int k0 = (s + 1) << 4;
            #pragma unroll
            for (int z = 0; z < ASUM; z++)
                va[z] = *(const float4*)(Ag + k0 + (size_t)z * AS);
            if (!TB) {
                const float* bp = B + (size_t)(kbase + k0 + bk) * ldb + col0 + bn;
                rb0 = *(const float4*)bp; rb1 = *(const float4*)(bp + 4);
            } else {
                const float* bp = B + (size_t)(col0 + tn) * ldb + kbase + k0 + tkh;
                rb0 = *(const float4*)bp; rb1 = *(const float4*)(bp + 4);
            }
        }
        #pragma unroll
        for (int kk = 0; kk < 16; kk++) {
            float a[4], b[4];
            #pragma unroll
            for (int i = 0; i < 4; i++) a[i] = As[cur][kk][ty + 8 * i];
            #pragma unroll
            for (int j = 0; j < 4; j++) b[j] = Bs[cur][kk][tx + 16 * j];
            #pragma unroll
            for (int i = 0; i < 4; i++)
                #pragma unroll
                for (int j = 0; j < 4; j++)
                    acc[i][j] = fmaf(a[i], b[j], acc[i][j]);
        }
        if (s + 1 < nst) {
            const int nxt = cur ^ 1;
            {
                float4 sv = va[0];
                #pragma unroll
                for (int z = 1; z < ASUM; z++) { sv.x += va[z].x; sv.y += va[z].y; sv.z += va[z].z; sv.w += va[z].w; }
                if (AEPI) {
                    sv.x = fmaxf(sv.x * invlen, 0.f); sv.y = fmaxf(sv.y * invlen, 0.f);
                    sv.z = fmaxf(sv.z * invlen, 0.f); sv.w = fmaxf(sv.w * invlen, 0.f);
                }
                As[nxt][akc+0][arow] = sv.x; As[nxt][akc+1][arow] = sv.y;
                As[nxt][akc+2][arow] = sv.z; As[nxt][akc+3][arow] = sv.w;
            }
            if (!TB) {
                *(float4*)&Bs[nxt][bk][bn]     = rb0;
                *(float4*)&Bs[nxt][bk][bn + 4] = rb1;
            } else {
                Bs[nxt][tkh+0][tn] = rb0.x; Bs[nxt][tkh+1][tn] = rb0.y;
                Bs[nxt][tkh+2][tn] = rb0.z; Bs[nxt][tkh+3][tn] = rb0.w;
                Bs[nxt][tkh+4][tn] = rb1.x; Bs[nxt][tkh+5][tn] = rb1.y;
                Bs[nxt][tkh+6][tn] = rb1.z; Bs[nxt][tkh+7][tn] = rb1.w;
            }
            __syncthreads();
        }
    }

    float* Cp = part + (size_t)bz * NBW * N;
    #pragma unroll
    for (int i = 0; i < 4; i++) {
        const int m = row0 + ty + 8 * i;
        #pragma unroll
        for (int j = 0; j < 4; j++) {
            const int n = col0 + tx + 16 * j;
            Cp[(size_t)m * N + n] = acc[i][j];
        }
    }
}

// ---------------------------------------------------------------------------
// Kernel 3: per-window attention; sums the 2 RPB partial slabs on load.
// ---------------------------------------------------------------------------
__global__ void __launch_bounds__(256) k3_attn(
    const float* __restrict__ x, const int* __restrict__ mask,
    const float* __restrict__ ps_ptr)
{
    int bw = blockIdx.x;
    int t = threadIdx.x;
    int warp = t >> 5, lane = t & 31;
    __shared__ float sr[DD];
    __shared__ float spb[NN];
    __shared__ float sdots[NN];
    __shared__ float red[NN];
    __shared__ float s_m, s_sum;

    const float* rp0 = g_P1 + (size_t)bw * NKB;
    const float* rp1 = rp0 + (size_t)NBW * NKB;
    {
        float4 a = ((const float4*)rp0)[t];
        float4 b = ((const float4*)rp1)[t];
        a.x += b.x; a.y += b.y; a.z += b.z; a.w += b.w;
        ((float4*)sr)[t] = a;
    }
    if (t < NN) spb[t] = rp0[DD + t] + rp1[DD + t];
    __syncthreads();

    const float* xw = x + (size_t)bw * NN * DD;
    float ps = ps_ptr[0];
    const float rs = 0.044194173824159216f;   // 512^-0.5

    #pragma unroll 4
    for (int j = warp; j < NN; j += 8) {
        const float4* row = (const float4*)(xw + (size_t)j * DD);
        const float4* r4  = (const float4*)sr;
        float s = 0.f;
        #pragma unroll
        for (int it = 0; it < 8; it++) {
            float4 v = row[lane + it * 32];
            float4 r = r4 [lane + it * 32];
            s += v.x*r.x + v.y*r.y + v.z*r.z + v.w*r.w;
        }
        #pragma unroll
        for (int o = 16; o > 0; o >>= 1) s += __shfl_xor_sync(0xffffffffu, s, o);
        if (lane == 0) {
            float d;
            if (mask[bw * NN + j] != 0) d = -FLT_MAX;
            else d = (s + ps * spb[j]) * rs;
            sdots[j] = d;
        }
    }
    __syncthreads();

    if (t < NN) red[t] = sdots[t];
    __syncthreads();
    for (int s = 64; s > 0; s >>= 1) {
        if (t < s) red[t] = fmaxf(red[t], red[t + s]);
        __syncthreads();
    }
    if (t == 0) s_m = red[0];
    __syncthreads();
    float m = s_m;
    if (t < NN) { float e = expf(sdots[t] - m); sdots[t] = e; red[t] = e; }
    __syncthreads();
    for (int s = 64; s > 0; s >>= 1) {
        if (t < s) red[t] += red[t + s];
        __syncthreads();
    }
    if (t == 0) s_sum = red[0];
    __syncthreads();
    float inv = 1.0f / s_sum;

    float4 acc = make_float4(0.f, 0.f, 0.f, 0.f);
    const float4* x4 = (const float4*)xw;
    #pragma unroll 8
    for (int j = 0; j < NN; j++) {
        float a = sdots[j] * inv;
        float4 v = x4[j * (DD/4) + t];
        acc.x += a*v.x; acc.y += a*v.y; acc.z += a*v.z; acc.w += a*v.w;
    }
    ((float4*)(g_Y + (size_t)bw * DD))[t] = acc;
}

// ---------------------------------------------------------------------------
// Kernel 5: sum the 8 O partial slabs, bos-shifted broadcast into out[...,1024:]
// ---------------------------------------------------------------------------
__global__ void __launch_bounds__(256) k5_bcast(
    const float* __restrict__ bos, float* __restrict__ out)
{
    int bw = blockIdx.x;
    int w  = bw & (WW - 1);
    int t  = threadIdx.x;
    float val;
    if (w == 0) {
        val = bos[t];
    } else {
        const float* p = g_P2 + (size_t)(bw - 1) * VV + t;
        val = 0.f;
        #pragma unroll
        for (int z = 0; z < 8; z++) val += p[(size_t)z * NBW * VV];
    }
    float* base = out + (size_t)bw * NN * OUTD + DD + t;
    #pragma unroll 4
    for (int j = 0; j < NN; j++) __stcs(&base[(size_t)j * OUTD], val);
}

// ---------------------------------------------------------------------------
extern "C" void kernel_launch(void* const* d_in, const int* in_sizes, int n_in,
                              void* d_out, int out_size) {
    const float* x    = (const float*)d_in[0];
    const int*   mask = (const int*)  d_in[1];
    const float* W_in = (const float*)d_in[2];
    const float* W_q  = (const float*)d_in[3];
    const float* W_k  = (const float*)d_in[4];
    const float* W_v  = (const float*)d_in[5];
    const float* psc  = (const float*)d_in[6];
    const float* bos  = (const float*)d_in[7];
    float* out = (float*)d_out;

    float *pS, *pLEN, *pKB, *pY, *pP1, *pP2;
    cudaGetSymbolAddress((void**)&pS,   g_S);
    cudaGetSymbolAddress((void**)&pLEN, g_LEN);
    cudaGetSymbolAddress((void**)&pKB,  g_KB);
    cudaGetSymbolAddress((void**)&pY,   g_Y);
    cudaGetSymbolAddress((void**)&pP1,  g_P1);
    cudaGetSymbolAddress((void**)&pP2,  g_P2);

    prep_kernel<<<(NKB*PP + 255)/256, 256>>>(W_k);
    k1_sum<<<NBW, 256>>>(x, mask);

    // F1: WE partials = S @ W_in (split 4) -> P1 ; copy rows [0, 16384)
    fgemm<false,1,0><<<CPB + 512, 128>>>(pS, W_in, pP1, PP, DD, PP, 256,
                                         8, nullptr, x, out, 0*CROWS);
    // F2: Q partials = relu(sum WE / len) @ W_q (split 4) -> P2 ; rows [16384, 32768)
    fgemm<false,4,1><<<CPB + 512, 128>>>(pP1, W_q, pP2, PP, PP, PP, 128,
                                         8, pLEN, x, out, 1*CROWS);
    // F3: RPB partials = (sum Q) @ KB^T (split 2) -> P1 ; rows [32768, 49152)
    fgemm<true,4,0><<<CPB + 576, 128>>>(pP2, pKB, pP1, NKB, PP, PP, 256,
                                        18, nullptr, x, out, 2*CROWS);

    k3_attn<<<NBW, 256>>>(x, mask, psc);

    // F4: O partials = Y @ W_v (split 8) -> P2 ; rows [49152, 65536)
    fgemm<false,1,0><<<CPB + 512, 128>>>(pY, W_v, pP2, VV, DD, VV, 128,
                                         4, nullptr, x, out, 3*CROWS);

    k5_bcast<<<NBW, 256>>>(bos, out);
}

// round 8
// speedup vs baseline: 2.0951x; 1.0020x over previous
#include <cuda_runtime.h>
#include <cuda_bf16.h>
#include <cfloat>
#include <cstddef>

// Problem constants
#define BB 8
#define WW 64
#define NN 128
#define DD 1024
#define PP 512
#define VV 256
#define NBW (BB*WW)          // 512 windows
#define OUTD (DD+VV)         // 1280
#define NKB (DD+NN)          // 1152 combined W_k rows + pos rows

// Scratch (device globals; no allocation allowed)
__device__ float g_S  [NBW*DD];      // masked sums per window
__device__ float g_LEN[NBW];         // valid lengths
__device__ float g_KB [NKB*PP];      // [W_k(1024 rows); POS(128 rows)] x 512
__device__ float g_Y  [NBW*DD];      // attn-weighted x sum
__device__ float g_P1 [2*NBW*NKB];   // partials: WE(4x512x512) / RPB(2x512x1152)
__device__ float g_P2 [4*NBW*PP];    // partials: Q(4x512x512)  / O(8x512x256)

// ---------------------------------------------------------------------------
// prep: W_k rows [0,1024) + sinusoidal pos rows [1024,1152) into g_KB
// ---------------------------------------------------------------------------
__global__ void prep_kernel(const float* __restrict__ Wk) {
    int idx = blockIdx.x * blockDim.x + threadIdx.x;
    if (idx >= NKB * PP) return;
    int row = idx >> 9;      // 0..1151
    int i   = idx & 511;
    if (row < DD) {
        g_KB[idx] = Wk[idx];
    } else {
        int j = row - DD;    // pos row 0..127
        const float LOG1E4 = 9.210340371976184f;
        float val;
        if (i < 256) {
            float invf = expf(-((float)i / 256.0f) * LOG1E4);
            val = sinf((float)j * invf);
        } else {
            float invf = expf(-((float)(i - 256) / 256.0f) * LOG1E4);
            val = cosf((float)j * invf);
        }
        g_KB[idx] = val;
    }
}

// ---------------------------------------------------------------------------
// Kernel 1: single pass over x — copy to out[..., :1024] (streaming stores),
// masked sum, length. One block per window; 2 rows in flight per thread.
// ---------------------------------------------------------------------------
__global__ void __launch_bounds__(256) k1_sum_copy(
    const float* __restrict__ x, const int* __restrict__ mask,
    float* __restrict__ out)
{
    int bw = blockIdx.x;
    int t  = threadIdx.x;
    __shared__ int smask[NN];
    if (t < NN) smask[t] = mask[bw * NN + t];
    __syncthreads();

    const float4* x4 = (const float4*)(x + (size_t)bw * NN * DD);
    float4* o4 = (float4*)(out + (size_t)bw * NN * OUTD);
    float4 acc0 = make_float4(0.f, 0.f, 0.f, 0.f);
    float4 acc1 = make_float4(0.f, 0.f, 0.f, 0.f);
    #pragma unroll 4
    for (int j = 0; j < 64; j++) {
        float4 v0 = x4[j * 256 + t];
        float4 v1 = x4[(j + 64) * 256 + t];
        __stcs(&o4[(size_t)j * 320 + t], v0);
        __stcs(&o4[(size_t)(j + 64) * 320 + t], v1);
        if (smask[j] == 0) {
            acc0.x += v0.x; acc0.y += v0.y; acc0.z += v0.z; acc0.w += v0.w;
        }
        if (smask[j + 64] == 0) {
            acc1.x += v1.x; acc1.y += v1.y; acc1.z += v1.z; acc1.w += v1.w;
        }
    }
    acc0.x += acc1.x; acc0.y += acc1.y; acc0.z += acc1.z; acc0.w += acc1.w;
    ((float4*)g_S)[bw * 256 + t] = acc0;
    if (t == 0) {
        int c = 0;
        #pragma unroll
        for (int j = 0; j < NN; j++) c += (smask[j] == 0);
        g_LEN[bw] = fmaxf((float)c, 1.0f);
    }
}

// ---------------------------------------------------------------------------
// Split-K GEMM with fused A-partial-sum input.
// grid = (gx, 16, SPLIT). 32x64 tile, 128 thr, 4x4 microtile, BK=16,
// double-buffered smem, register prefetch, one sync per stage.
// A := sum of ASUM slabs (slab stride NBW*lda); AEPI==1: relu(sum/len[row]).
// Output: partial slab part[bz][M][N] (consumer sums slabs).
// ---------------------------------------------------------------------------
template<bool TB, int ASUM, int AEPI>
__global__ void __launch_bounds__(128) gemm_sk(
    const float* __restrict__ A, const float* __restrict__ B,
    float* __restrict__ part, int N, int lda, int ldb, int Kchunk,
    const float* __restrict__ lenv)
{
    __shared__ float As[2][16][33];
    __shared__ float Bs[2][16][68];
    const int tid = threadIdx.x;
    const int row0  = blockIdx.y * 32;
    const int col0  = blockIdx.x * 64;
    const int kbase = blockIdx.z * Kchunk;

    const int ty = tid >> 4;          // 0..7
    const int tx = tid & 15;          // 0..15

    const int arow = tid >> 2;        // 0..31
    const int akc  = (tid & 3) << 2;  // 0,4,8,12
    const size_t AS = (size_t)NBW * lda;
    const float* Ag = A + (size_t)(row0 + arow) * lda + kbase + akc;
    float invlen = 1.0f;
    if (AEPI) invlen = 1.0f / lenv[row0 + arow];

    const int bk  = tid >> 3;         // !TB: 0..15
    const int bn  = (tid & 7) << 3;   // !TB
    const int tn  = tid & 63;         // TB
    const int tkh = (tid >> 6) << 3;  // TB: 0 or 8

    float acc[4][4] = {};
    float4 va[ASUM];
    float4 rb0, rb1;

    // ---- prologue loads (stage 0) ----
    #pragma unroll
    for (int z = 0; z < ASUM; z++) va[z] = *(const float4*)(Ag + (size_t)z * AS);
    if (!TB) {
        const float* bp = B + (size_t)(kbase + bk) * ldb + col0 + bn;
        rb0 = *(const float4*)bp; rb1 = *(const float4*)(bp + 4);
    } else {
        const float* bp = B + (size_t)(col0 + tn) * ldb + kbase + tkh;
        rb0 = *(const float4*)bp; rb1 = *(const float4*)(bp + 4);
    }
    {
        float4 s = va[0];
        #pragma unroll
        for (int z = 1; z < ASUM; z++) { s.x += va[z].x; s.y += va[z].y; s.z += va[z].z; s.w += va[z].w; }
        if (AEPI) {
            s.x = fmaxf(s.x * invlen, 0.f); s.y = fmaxf(s.y * invlen, 0.f);
            s.z = fmaxf(s.z * invlen, 0.f); s.w = fmaxf(s.w * invlen, 0.f);
        }
        As[0][akc+0][arow] = s.x; As[0][akc+1][arow] = s.y;
        As[0][akc+2][arow] = s.z; As[0][akc+3][arow] = s.w;
    }
    if (!TB) {
        *(float4*)&Bs[0][bk][bn]     = rb0;
        *(float4*)&Bs[0][bk][bn + 4] = rb1;
    } else {
        Bs[0][tkh+0][tn] = rb0.x; Bs[0][tkh+1][tn] = rb0.y;
        Bs[0][tkh+2][tn] = rb0.z; Bs[0][tkh+3][tn] = rb0.w;
        Bs[0][tkh+4][tn] = rb1.x; Bs[0][tkh+5][tn] = rb1.y;
        Bs[0][tkh+6][tn] = rb1.z; Bs[0][tkh+7][tn] = rb1.w;
    }
    __syncthreads();

    const int nst = Kchunk >> 4;
    for (int s = 0; s < nst; s++) {
        const int cur = s & 1;
        if (s + 1 < nst) {
            const int k0 = (s + 1) << 4;
            #pragma unroll
            for (int z = 0; z < ASUM; z++)
                va[z] = *(const float4*)(Ag + k0 + (size_t)z * AS);
            if (!TB) {
                const float* bp = B + (size_t)(kbase + k0 + bk) * ldb + col0 + bn;
                rb0 = *(const float4*)bp; rb1 = *(const float4*)(bp + 4);
            } else {
                const float* bp = B + (size_t)(col0 + tn) * ldb + kbase + k0 + tkh;
                rb0 = *(const float4*)bp; rb1 = *(const float4*)(bp + 4);
            }
        }
        #pragma unroll
        for (int kk = 0; kk < 16; kk++) {
            float a[4], b[4];
            #pragma unroll
            for (int i = 0; i < 4; i++) a[i] = As[cur][kk][ty + 8 * i];
            #pragma unroll
            for (int j = 0; j < 4; j++) b[j] = Bs[cur][kk][tx + 16 * j];
            #pragma unroll
            for (int i = 0; i < 4; i++)
                #pragma unroll
                for (int j = 0; j < 4; j++)
                    acc[i][j] = fmaf(a[i], b[j], acc[i][j]);
        }
        if (s + 1 < nst) {
            const int nxt = cur ^ 1;
            {
                float4 sv = va[0];
                #pragma unroll
                for (int z = 1; z < ASUM; z++) { sv.x += va[z].x; sv.y += va[z].y; sv.z += va[z].z; sv.w += va[z].w; }
                if (AEPI) {
                    sv.x = fmaxf(sv.x * invlen, 0.f); sv.y = fmaxf(sv.y * invlen, 0.f);
                    sv.z = fmaxf(sv.z * invlen, 0.f); sv.w = fmaxf(sv.w * invlen, 0.f);
                }
                As[nxt][akc+0][arow] = sv.x; As[nxt][akc+1][arow] = sv.y;
                As[nxt][akc+2][arow] = sv.z; As[nxt][akc+3][arow] = sv.w;
            }
            if (!TB) {
                *(float4*)&Bs[nxt][bk][bn]     = rb0;
                *(float4*)&Bs[nxt][bk][bn + 4] = rb1;
            } else {
                Bs[nxt][tkh+0][tn] = rb0.x; Bs[nxt][tkh+1][tn] = rb0.y;
                Bs[nxt][tkh+2][tn] = rb0.z; Bs[nxt][tkh+3][tn] = rb0.w;
                Bs[nxt][tkh+4][tn] = rb1.x; Bs[nxt][tkh+5][tn] = rb1.y;
                Bs[nxt][tkh+6][tn] = rb1.z; Bs[nxt][tkh+7][tn] = rb1.w;
            }
            __syncthreads();
        }
    }

    float* Cp = part + (size_t)blockIdx.z * NBW * N;
    #pragma unroll
    for (int i = 0; i < 4; i++) {
        const int m = row0 + ty + 8 * i;
        #pragma unroll
        for (int j = 0; j < 4; j++) {
            const int n = col0 + tx + 16 * j;
            Cp[(size_t)m * N + n] = acc[i][j];
        }
    }
}

// ---------------------------------------------------------------------------
// Kernel 3: per-window attention; sums the 2 RPB partial slabs on load.
// Dots phase: each warp handles row pairs (j, j+64) for 2x load MLP.
// ---------------------------------------------------------------------------
__global__ void __launch_bounds__(256) k3_attn(
    const float* __restrict__ x, const int* __restrict__ mask,
    const float* __restrict__ ps_ptr)
{
    int bw = blockIdx.x;
    int t = threadIdx.x;
    int warp = t >> 5, lane = t & 31;
    __shared__ float sr[DD];
    __shared__ float spb[NN];
    __shared__ float sdots[NN];
    __shared__ float red[NN];
    __shared__ float s_m, s_sum;

    const float* rp0 = g_P1 + (size_t)bw * NKB;
    const float* rp1 = rp0 + (size_t)NBW * NKB;
    {
        float4 a = ((const float4*)rp0)[t];
        float4 b = ((const float4*)rp1)[t];
        a.x += b.x; a.y += b.y; a.z += b.z; a.w += b.w;
        ((float4*)sr)[t] = a;
    }
    if (t < NN) spb[t] = rp0[DD + t] + rp1[DD + t];
    __syncthreads();

    const float* xw = x + (size_t)bw * NN * DD;
    float ps = ps_ptr[0];
    const float rs = 0.044194173824159216f;   // 512^-0.5

    for (int j = warp; j < 64; j += 8) {
        const float4* row0 = (const float4*)(xw + (size_t)j * DD);
        const float4* row1 = (const float4*)(xw + (size_t)(j + 64) * DD);
        const float4* r4   = (const float4*)sr;
        float s0 = 0.f, s1 = 0.f;
        #pragma unroll
        for (int it = 0; it < 8; it++) {
            float4 v0 = row0[lane + it * 32];
            float4 v1 = row1[lane + it * 32];
            float4 r  = r4  [lane + it * 32];
            s0 += v0.x*r.x + v0.y*r.y + v0.z*r.z + v0.w*r.w;
            s1 += v1.x*r.x + v1.y*r.y + v1.z*r.z + v1.w*r.w;
        }
        #pragma unroll
        for (int o = 16; o > 0; o >>= 1) {
            s0 += __shfl_xor_sync(0xffffffffu, s0, o);
            s1 += __shfl_xor_sync(0xffffffffu, s1, o);
        }
        if (lane == 0) {
            sdots[j]      = (mask[bw * NN + j]      != 0) ? -FLT_MAX : (s0 + ps * spb[j])      * rs;
            sdots[j + 64] = (mask[bw * NN + j + 64] != 0) ? -FLT_MAX : (s1 + ps * spb[j + 64]) * rs;
        }
    }
    __syncthreads();

    if (t < NN) red[t] = sdots[t];
    __syncthreads();
    for (int s = 64; s > 0; s >>= 1) {
        if (t < s) red[t] = fmaxf(red[t], red[t + s]);
        __syncthreads();
    }
    if (t == 0) s_m = red[0];
    __syncthreads();
    float m = s_m;
    if (t < NN) { float e = expf(sdots[t] - m); sdots[t] = e; red[t] = e; }
    __syncthreads();
    for (int s = 64; s > 0; s >>= 1) {
        if (t < s) red[t] += red[t + s];
        __syncthreads();
    }
    if (t == 0) s_sum = red[0];
    __syncthreads();
    float inv = 1.0f / s_sum;

    float4 acc = make_float4(0.f, 0.f, 0.f, 0.f);
    const float4* x4 = (const float4*)xw;
    #pragma unroll 8
    for (int j = 0; j < NN; j++) {
        float a = sdots[j] * inv;
        float4 v = x4[j * (DD/4) + t];
        acc.x += a*v.x; acc.y += a*v.y; acc.z += a*v.z; acc.w += a*v.w;
    }
    ((float4*)(g_Y + (size_t)bw * DD))[t] = acc;
}

// ---------------------------------------------------------------------------
// Kernel 5: sum the 8 O partial slabs, bos-shifted broadcast into out[...,1024:]
// ---------------------------------------------------------------------------
__global__ void __launch_bounds__(256) k5_bcast(
    const float* __restrict__ bos, float* __restrict__ out)
{
    int bw = blockIdx.x;
    int w  = bw & (WW - 1);
    int t  = threadIdx.x;
    float val;
    if (w == 0) {
        val = bos[t];
    } else {
        const float* p = g_P2 + (size_t)(bw - 1) * VV + t;
        val = 0.f;
        #pragma unroll
        for (int z = 0; z < 8; z++) val += p[(size_t)z * NBW * VV];
    }
    float* base = out + (size_t)bw * NN * OUTD + DD + t;
    #pragma unroll 4
    for (int j = 0; j < NN; j++) __stcs(&base[(size_t)j * OUTD], val);
}

// ---------------------------------------------------------------------------
extern "C" void kernel_launch(void* const* d_in, const int* in_sizes, int n_in,
                              void* d_out, int out_size) {
    const float* x    = (const float*)d_in[0];
    const int*   mask = (const int*)  d_in[1];
    const float* W_in = (const float*)d_in[2];
    const float* W_q  = (const float*)d_in[3];
    const float* W_k  = (const float*)d_in[4];
    const float* W_v  = (const float*)d_in[5];
    const float* psc  = (const float*)d_in[6];
    const float* bos  = (const float*)d_in[7];
    float* out = (float*)d_out;

    float *pS, *pLEN, *pKB, *pY, *pP1, *pP2;
    cudaGetSymbolAddress((void**)&pS,   g_S);
    cudaGetSymbolAddress((void**)&pLEN, g_LEN);
    cudaGetSymbolAddress((void**)&pKB,  g_KB);
    cudaGetSymbolAddress((void**)&pY,   g_Y);
    cudaGetSymbolAddress((void**)&pP1,  g_P1);
    cudaGetSymbolAddress((void**)&pP2,  g_P2);

    prep_kernel<<<(NKB*PP + 255)/256, 256>>>(W_k);
    k1_sum_copy<<<NBW, 256>>>(x, mask, out);

    // F1: WE partials = S @ W_in          split 4 -> 512 blocks
    gemm_sk<false,1,0><<<dim3(8, 16, 4), 128>>>(pS,  W_in, pP1, PP,  DD, PP, 256, nullptr);
    // F2: Q partials = relu(sumWE/len)@W_q split 4 -> 512 blocks
    gemm_sk<false,4,1><<<dim3(8, 16, 4), 128>>>(pP1, W_q,  pP2, PP,  PP, PP, 128, pLEN);
    // F3: RPB partials = (sumQ) @ KB^T    split 2 -> 576 blocks
    gemm_sk<true, 4,0><<<dim3(18,16, 2), 128>>>(pP2, pKB,  pP1, NKB, PP, PP, 256, nullptr);

    k3_attn<<<NBW, 256>>>(x, mask, psc);

    // F4: O partials = Y @ W_v            split 8 -> 512 blocks
    gemm_sk<false,1,0><<<dim3(4, 16, 8), 128>>>(pY,  W_v,  pP2, VV,  DD, VV, 128, nullptr);

    k5_bcast<<<NBW, 256>>>(bos, out);
}